// round 1
// baseline (speedup 1.0000x reference)
#include <cuda_runtime.h>
#include <cuda_bf16.h>

// Problem constants
#define SEQ 2048
#define DD  1024           // D
#define MM  256            // mentions
#define FF1_ 1024
#define FF2_ 512
#define OUTW 128

// Scratch: A[i] = left_i @ W1[0:2048],  B[j] = left_j @ W1[2048:4096] + b1
__device__ float g_A[MM * FF1_];
__device__ float g_B[MM * FF1_];

// ---------------- packed f32x2 helpers (sm_100a) ----------------
__device__ __forceinline__ unsigned long long fma2(unsigned long long a,
                                                   unsigned long long b,
                                                   unsigned long long c) {
    unsigned long long d;
    asm("fma.rn.f32x2 %0, %1, %2, %3;" : "=l"(d) : "l"(a), "l"(b), "l"(c));
    return d;
}
__device__ __forceinline__ unsigned long long pack2(float lo, float hi) {
    unsigned long long r;
    asm("mov.b64 %0, {%1, %2};" : "=l"(r) : "f"(lo), "f"(hi));
    return r;
}
__device__ __forceinline__ float2 unpack2(unsigned long long v) {
    float2 f;
    asm("mov.b64 {%0, %1}, %2;" : "=f"(f.x), "=f"(f.y) : "l"(v));
    return f;
}

// ================================================================
// Kernel A: C[256][2048] tiled GEMM, K=2048.
//   cols [0,1024)   -> g_A  (uses W1 rows [0,2048))
//   cols [1024,2048)-> g_B  (uses W1 rows [2048,4096)) + b1
// l[m][k] = emb[begin[m]][k] (k<1024) else emb[end[m]][k-1024]
// Grid (32 n-tiles, 4 m-tiles), 256 threads, 64x64 tile, KC=16.
// ================================================================
__global__ __launch_bounds__(256) void precompute_ab(
    const float* __restrict__ emb,
    const int*   __restrict__ bidx,
    const int*   __restrict__ eidx,
    const float* __restrict__ W1,
    const float* __restrict__ b1)
{
    __shared__ float ls[16][68];   // [k][m], padded pitch (16B-aligned rows)
    __shared__ float ws[16][64];   // [k][n]

    const int n0 = blockIdx.x * 64;
    const int m0 = blockIdx.y * 64;
    const int tid = threadIdx.x;
    const int ty = tid >> 4, tx = tid & 15;

    float acc[4][4];
#pragma unroll
    for (int a = 0; a < 4; a++)
#pragma unroll
        for (int b = 0; b < 4; b++) acc[a][b] = 0.f;

    const int lm  = tid & 63;            // m for ls load
    const int lkq = (tid >> 6) * 4;      // k quad for ls load
    const int wk  = tid >> 4;            // k for ws load
    const int wn  = (tid & 15) * 4;      // n quad for ws load

    for (int k0 = 0; k0 < 2048; k0 += 16) {
        // ---- load l tile (transposed into [k][m]) ----
        {
            const int gk  = k0 + lkq;
            const int row = (gk < 1024) ? bidx[m0 + lm] : eidx[m0 + lm];
            const int col = gk & 1023;
            float4 lv = *(const float4*)&emb[row * DD + col];
            ls[lkq + 0][lm] = lv.x;
            ls[lkq + 1][lm] = lv.y;
            ls[lkq + 2][lm] = lv.z;
            ls[lkq + 3][lm] = lv.w;
        }
        // ---- load W tile ----
        {
            const int gn = n0 + wn;
            const float* src = (gn < 1024)
                ? (W1 + (size_t)(k0 + wk) * 1024 + gn)
                : (W1 + (size_t)(2048 + k0 + wk) * 1024 + (gn - 1024));
            *(float4*)&ws[wk][wn] = *(const float4*)src;
        }
        __syncthreads();
#pragma unroll
        for (int k = 0; k < 16; k++) {
            float a[4], b[4];
            *(float4*)a = *(const float4*)&ls[k][ty * 4];
            *(float4*)b = *(const float4*)&ws[k][tx * 4];
#pragma unroll
            for (int mm2 = 0; mm2 < 4; mm2++)
#pragma unroll
                for (int nn2 = 0; nn2 < 4; nn2++)
                    acc[mm2][nn2] = fmaf(a[mm2], b[nn2], acc[mm2][nn2]);
        }
        __syncthreads();
    }

#pragma unroll
    for (int mm2 = 0; mm2 < 4; mm2++) {
#pragma unroll
        for (int nn2 = 0; nn2 < 4; nn2++) {
            const int m = m0 + ty * 4 + mm2;
            const int n = n0 + tx * 4 + nn2;
            if (n < 1024) g_A[m * 1024 + n] = acc[mm2][nn2];
            else          g_B[m * 1024 + (n - 1024)] = acc[mm2][nn2] + b1[n - 1024];
        }
    }
}

// ================================================================
// Kernel B: fused (h1 gen) -> GEMM2(K=1024,N=512)+ReLU -> GEMM3(K=512,N=128)
// One CTA = 32 consecutive pair-rows (fixed i, j in [j0, j0+32)).
// 128 threads = 4 warps. Warp w owns rows w*8..w*8+7 (a-frags broadcast).
// GEMM2 thread tile 8x16 (cols l*4 + q*128). f32x2 packed FMA.
// Dynamic smem layout (floats):
//   h1s  [32][36]   @ 0      (1152)    phase 1
//   w2s  [32][512]  @ 1152   (16384)   phase 1
//   h2sT [512][36]  @ 17536  (18432)   phase 2/3 (cols-major, broadcast reads)
//   wos  [64][128]  @ 0      (8192)    phase 3 (overlaps dead h1s/w2s)
// Total 36992 floats = 147968 bytes.
// ================================================================
#define SMEM_FLOATS 36992

__global__ __launch_bounds__(128, 1) void pair_ffnn(
    const float* __restrict__ W2,
    const float* __restrict__ b2,
    const float* __restrict__ Wo,
    const float* __restrict__ bo,
    float* __restrict__ out)
{
    extern __shared__ float smem[];
    float* h1s  = smem;           // [32][36]
    float* w2s  = smem + 1152;    // [32][512]
    float* h2sT = smem + 17536;   // [512][36]
    float* wos  = smem;           // [64][128] (phase 3)

    const int tid = threadIdx.x;
    const int w = tid >> 5;       // warp 0..3
    const int l = tid & 31;       // lane
    const int r0 = blockIdx.x * 32;
    const int i  = r0 >> 8;
    const int j0 = r0 & 255;

    const float* __restrict__ Arow = g_A + (size_t)i * 1024;

    unsigned long long acc2[8][8];
#pragma unroll
    for (int a = 0; a < 8; a++)
#pragma unroll
        for (int b = 0; b < 8; b++) acc2[a][b] = 0ull;

    // ---------------- Phase 1: GEMM2 over K=1024 in chunks of 32 ----------------
    for (int kc = 0; kc < 32; kc++) {
        const int k0 = kc * 32;

        // load W2 chunk [32][512] (4096 float4 / 128 threads)
#pragma unroll
        for (int t = 0; t < 32; t++) {
            const int idx = t * 128 + tid;
            const int kk = idx >> 7;
            const int nn = (idx & 127) << 2;
            *(float4*)&w2s[kk * 512 + nn] =
                *(const float4*)&W2[(size_t)(k0 + kk) * 512 + nn];
        }
        // build h1 tile [k][m] = relu(A[i][k] + B[j0+m][k])  (256 float4 tasks)
#pragma unroll
        for (int t = 0; t < 2; t++) {
            const int idx = t * 128 + tid;
            const int m  = idx >> 3;
            const int kq = (idx & 7) << 2;
            float4 bv = *(const float4*)&g_B[(size_t)(j0 + m) * 1024 + k0 + kq];
            float4 av = *(const float4*)&Arow[k0 + kq];
            h1s[(kq + 0) * 36 + m] = fmaxf(av.x + bv.x, 0.f);
            h1s[(kq + 1) * 36 + m] = fmaxf(av.y + bv.y, 0.f);
            h1s[(kq + 2) * 36 + m] = fmaxf(av.z + bv.z, 0.f);
            h1s[(kq + 3) * 36 + m] = fmaxf(av.w + bv.w, 0.f);
        }
        __syncthreads();

#pragma unroll 4
        for (int k = 0; k < 32; k++) {
            float4 a0 = *(const float4*)&h1s[k * 36 + w * 8];      // broadcast
            float4 a1 = *(const float4*)&h1s[k * 36 + w * 8 + 4];  // broadcast
            unsigned long long av[8];
            av[0] = pack2(a0.x, a0.x); av[1] = pack2(a0.y, a0.y);
            av[2] = pack2(a0.z, a0.z); av[3] = pack2(a0.w, a0.w);
            av[4] = pack2(a1.x, a1.x); av[5] = pack2(a1.y, a1.y);
            av[6] = pack2(a1.z, a1.z); av[7] = pack2(a1.w, a1.w);
            unsigned long long bv[8];
#pragma unroll
            for (int q = 0; q < 4; q++) {
                float4 b4 = *(const float4*)&w2s[k * 512 + q * 128 + l * 4];
                bv[2 * q]     = pack2(b4.x, b4.y);
                bv[2 * q + 1] = pack2(b4.z, b4.w);
            }
#pragma unroll
            for (int mm2 = 0; mm2 < 8; mm2++)
#pragma unroll
                for (int p = 0; p < 8; p++)
                    acc2[mm2][p] = fma2(av[mm2], bv[p], acc2[mm2][p]);
        }
        __syncthreads();
    }

    // ---------------- Phase 2: h2 = relu(acc + b2) -> h2sT [col][row] ----------------
#pragma unroll
    for (int p = 0; p < 8; p++) {
        const int c0 = (p >> 1) * 128 + l * 4 + (p & 1) * 2;
        const float bb0 = __ldg(&b2[c0]);
        const float bb1 = __ldg(&b2[c0 + 1]);
#pragma unroll
        for (int mm2 = 0; mm2 < 8; mm2++) {
            float2 v = unpack2(acc2[mm2][p]);
            h2sT[c0 * 36 + w * 8 + mm2]       = fmaxf(v.x + bb0, 0.f);
            h2sT[(c0 + 1) * 36 + w * 8 + mm2] = fmaxf(v.y + bb1, 0.f);
        }
    }

    // ---------------- Phase 3: GEMM3 (K=512, N=128) ----------------
    unsigned long long acc3[8][2];
#pragma unroll
    for (int a = 0; a < 8; a++) { acc3[a][0] = 0ull; acc3[a][1] = 0ull; }

    for (int kc = 0; kc < 8; kc++) {
        const int k0 = kc * 64;
        __syncthreads();  // h2sT writes visible (kc=0) / previous wos readers done
        // load Wo chunk [64][128] (2048 float4 / 128 threads)
#pragma unroll
        for (int t = 0; t < 16; t++) {
            const int idx = t * 128 + tid;
            const int kk = idx >> 5;
            const int nn = (idx & 31) << 2;
            *(float4*)&wos[kk * 128 + nn] =
                *(const float4*)&Wo[(size_t)(k0 + kk) * 128 + nn];
        }
        __syncthreads();

#pragma unroll 8
        for (int k = 0; k < 64; k++) {
            float4 a0 = *(const float4*)&h2sT[(k0 + k) * 36 + w * 8];      // broadcast
            float4 a1 = *(const float4*)&h2sT[(k0 + k) * 36 + w * 8 + 4];  // broadcast
            unsigned long long av[8];
            av[0] = pack2(a0.x, a0.x); av[1] = pack2(a0.y, a0.y);
            av[2] = pack2(a0.z, a0.z); av[3] = pack2(a0.w, a0.w);
            av[4] = pack2(a1.x, a1.x); av[5] = pack2(a1.y, a1.y);
            av[6] = pack2(a1.z, a1.z); av[7] = pack2(a1.w, a1.w);
            float4 b4 = *(const float4*)&wos[k * 128 + l * 4];
            unsigned long long bv0 = pack2(b4.x, b4.y);
            unsigned long long bv1 = pack2(b4.z, b4.w);
#pragma unroll
            for (int mm2 = 0; mm2 < 8; mm2++) {
                acc3[mm2][0] = fma2(av[mm2], bv0, acc3[mm2][0]);
                acc3[mm2][1] = fma2(av[mm2], bv1, acc3[mm2][1]);
            }
        }
    }

    // ---------------- Epilogue: out = acc3 + bo ----------------
    const float4 bov = *(const float4*)&bo[l * 4];
#pragma unroll
    for (int mm2 = 0; mm2 < 8; mm2++) {
        const int r = r0 + w * 8 + mm2;
        float2 v0 = unpack2(acc3[mm2][0]);
        float2 v1 = unpack2(acc3[mm2][1]);
        float4 o = make_float4(v0.x + bov.x, v0.y + bov.y,
                               v1.x + bov.z, v1.y + bov.w);
        *(float4*)&out[(size_t)r * OUTW + l * 4] = o;
    }
}

// ================================================================
extern "C" void kernel_launch(void* const* d_in, const int* in_sizes, int n_in,
                              void* d_out, int out_size) {
    const float* emb  = (const float*)d_in[0];
    const int*   bidx = (const int*)  d_in[1];
    const int*   eidx = (const int*)  d_in[2];
    const float* W1   = (const float*)d_in[3];
    const float* b1   = (const float*)d_in[4];
    const float* W2   = (const float*)d_in[5];
    const float* b2   = (const float*)d_in[6];
    const float* Wo   = (const float*)d_in[7];
    const float* bo   = (const float*)d_in[8];
    float* out = (float*)d_out;

    dim3 gA(32, 4);
    precompute_ab<<<gA, 256>>>(emb, bidx, eidx, W1, b1);

    cudaFuncSetAttribute(pair_ffnn,
                         cudaFuncAttributeMaxDynamicSharedMemorySize,
                         SMEM_FLOATS * sizeof(float));
    pair_ffnn<<<2048, 128, SMEM_FLOATS * sizeof(float)>>>(W2, b2, Wo, bo, out);
}

// round 3
// speedup vs baseline: 2.9364x; 2.9364x over previous
#include <cuda_runtime.h>
#include <cstdint>

#define OUTW 128

// ---------------- device scratch ----------------
__device__ float g_A[256 * 1024];        // left_i @ W1_top
__device__ float g_B[256 * 1024];        // left_j @ W1_bot + b1
__device__ float g_W2T[512 * 1024];      // W2^T (tf32-rounded)
__device__ float g_WoT[128 * 512];       // Wo^T (tf32-rounded)
__device__ float g_h2[65536ull * 512];   // relu(h1@W2+b2), tf32-rounded

// ---------------- helpers ----------------
__device__ __forceinline__ uint32_t f2tf32(float x) {
    uint32_t u;
    asm("cvt.rna.tf32.f32 %0, %1;" : "=r"(u) : "f"(x));
    return u;
}
__device__ __forceinline__ float tf32f(float x) {
    return __uint_as_float(f2tf32(x));
}
__device__ __forceinline__ uint32_t smem_u32(const void* p) {
    uint32_t a;
    asm("{ .reg .u64 t; cvta.to.shared.u64 t, %1; cvt.u32.u64 %0, t; }"
        : "=r"(a) : "l"(p));
    return a;
}
__device__ __forceinline__ void cp16(uint32_t s, const void* g) {
    asm volatile("cp.async.cg.shared.global [%0], [%1], 16;" :: "r"(s), "l"(g));
}
#define CP_COMMIT() asm volatile("cp.async.commit_group;" ::: "memory")
#define CP_WAIT0()  asm volatile("cp.async.wait_group 0;" ::: "memory")

// D += A(16x8,row) * B(8x8,col)  tf32
__device__ __forceinline__ void mma1688(float d[4], const uint32_t a[4],
                                        uint32_t b0, uint32_t b1) {
    asm volatile(
        "mma.sync.aligned.m16n8k8.row.col.f32.tf32.tf32.f32 "
        "{%0,%1,%2,%3}, {%4,%5,%6,%7}, {%8,%9}, {%0,%1,%2,%3};"
        : "+f"(d[0]), "+f"(d[1]), "+f"(d[2]), "+f"(d[3])
        : "r"(a[0]), "r"(a[1]), "r"(a[2]), "r"(a[3]), "r"(b0), "r"(b1));
}

// ================================================================
// Kernel 1 (validated in round 1): A = left@W1_top, B = left@W1_bot + b1
// ================================================================
__global__ __launch_bounds__(256) void precompute_ab(
    const float* __restrict__ emb,
    const int*   __restrict__ bidx,
    const int*   __restrict__ eidx,
    const float* __restrict__ W1,
    const float* __restrict__ b1)
{
    __shared__ float ls[16][68];
    __shared__ float ws[16][64];

    const int n0 = blockIdx.x * 64;
    const int m0 = blockIdx.y * 64;
    const int tid = threadIdx.x;
    const int ty = tid >> 4, tx = tid & 15;

    float acc[4][4];
#pragma unroll
    for (int a = 0; a < 4; a++)
#pragma unroll
        for (int b = 0; b < 4; b++) acc[a][b] = 0.f;

    const int lm  = tid & 63;
    const int lkq = (tid >> 6) * 4;
    const int wk  = tid >> 4;
    const int wn  = (tid & 15) * 4;

    for (int k0 = 0; k0 < 2048; k0 += 16) {
        {
            const int gk  = k0 + lkq;
            const int row = (gk < 1024) ? bidx[m0 + lm] : eidx[m0 + lm];
            const int col = gk & 1023;
            float4 lv = *(const float4*)&emb[row * 1024 + col];
            ls[lkq + 0][lm] = lv.x;
            ls[lkq + 1][lm] = lv.y;
            ls[lkq + 2][lm] = lv.z;
            ls[lkq + 3][lm] = lv.w;
        }
        {
            const int gn = n0 + wn;
            const float* src = (gn < 1024)
                ? (W1 + (size_t)(k0 + wk) * 1024 + gn)
                : (W1 + (size_t)(2048 + k0 + wk) * 1024 + (gn - 1024));
            *(float4*)&ws[wk][wn] = *(const float4*)src;
        }
        __syncthreads();
#pragma unroll
        for (int k = 0; k < 16; k++) {
            float a[4], b[4];
            *(float4*)a = *(const float4*)&ls[k][ty * 4];
            *(float4*)b = *(const float4*)&ws[k][tx * 4];
#pragma unroll
            for (int m2 = 0; m2 < 4; m2++)
#pragma unroll
                for (int n2 = 0; n2 < 4; n2++)
                    acc[m2][n2] = fmaf(a[m2], b[n2], acc[m2][n2]);
        }
        __syncthreads();
    }

#pragma unroll
    for (int m2 = 0; m2 < 4; m2++)
#pragma unroll
        for (int n2 = 0; n2 < 4; n2++) {
            const int m = m0 + ty * 4 + m2;
            const int n = n0 + tx * 4 + n2;
            if (n < 1024) g_A[m * 1024 + n] = acc[m2][n2];
            else          g_B[m * 1024 + (n - 1024)] = acc[m2][n2] + b1[n - 1024];
        }
}

// ================================================================
// Kernel 2: transpose + tf32 round:  src[R][C] fp32 -> dst[C][R] tf32
// ================================================================
__global__ __launch_bounds__(256) void transpose_cvt(const float* __restrict__ src,
                                                     float* __restrict__ dst,
                                                     int R, int C)
{
    __shared__ float t[32][33];
    const int c0 = blockIdx.x * 32, r0 = blockIdx.y * 32;
    const int x = threadIdx.x & 31, y = threadIdx.x >> 5;
#pragma unroll
    for (int dy = 0; dy < 32; dy += 8)
        t[y + dy][x] = src[(size_t)(r0 + y + dy) * C + c0 + x];
    __syncthreads();
#pragma unroll
    for (int dy = 0; dy < 32; dy += 8)
        dst[(size_t)(c0 + y + dy) * R + r0 + x] = tf32f(t[x][y + dy]);
}

// ================================================================
// Kernel 3: GEMM2 — h2 = tf32(relu(h1 @ W2 + b2))
// CTA: 512 thr, tile M=128 x N=256, K=1024 (32 chunks of 32, dbuf).
// Warp grid 4m x 4n, warp tile 32x64 (2 m-frags x 8 n-frags).
// smem pitch 36 floats -> conflict-free frag LDS, 16B-aligned rows.
// ================================================================
#define SA_PITCH 36
#define G2_SMEM ((2 * 128 * SA_PITCH + 2 * 256 * SA_PITCH) * 4)

__global__ __launch_bounds__(512, 1) void gemm2(const float* __restrict__ b2)
{
    extern __shared__ float sm[];
    float* sA = sm;                          // [2][128][36]
    float* sB = sm + 2 * 128 * SA_PITCH;     // [2][256][36]

    const int tid = threadIdx.x, w = tid >> 5, l = tid & 31;
    const int g = l >> 2, tg = l & 3;
    const int wm = w >> 2, wn = w & 3;

    const int rb = blockIdx.x >> 1, nh = blockIdx.x & 1;
    const size_t r0 = (size_t)rb * 128;
    const int i = rb >> 1, j0 = (rb & 1) * 128, nbase = nh * 256;
    const float* __restrict__ Arow = g_A + (size_t)i * 1024;

    float acc[2][8][4];
#pragma unroll
    for (int mt = 0; mt < 2; mt++)
#pragma unroll
        for (int nt = 0; nt < 8; nt++)
#pragma unroll
            for (int q = 0; q < 4; q++) acc[mt][nt][q] = 0.f;

    // prologue: stage chunk 0
    {
        const int k0 = 0;
#pragma unroll
        for (int t = 0; t < 2; t++) {
            const int idx = t * 512 + tid;
            const int m = idx >> 3, kq = (idx & 7) * 4;
            float4 bv = *(const float4*)&g_B[(size_t)(j0 + m) * 1024 + k0 + kq];
            float4 av = *(const float4*)&Arow[k0 + kq];
            float4 h = make_float4(tf32f(fmaxf(av.x + bv.x, 0.f)),
                                   tf32f(fmaxf(av.y + bv.y, 0.f)),
                                   tf32f(fmaxf(av.z + bv.z, 0.f)),
                                   tf32f(fmaxf(av.w + bv.w, 0.f)));
            *(float4*)&sA[m * SA_PITCH + kq] = h;
        }
        const uint32_t dstb = smem_u32(sB);
#pragma unroll
        for (int t = 0; t < 4; t++) {
            const int idx = t * 512 + tid;
            const int n = idx >> 3, kq = (idx & 7) * 4;
            cp16(dstb + (n * SA_PITCH + kq) * 4,
                 &g_W2T[(size_t)(nbase + n) * 1024 + k0 + kq]);
        }
        CP_COMMIT();
        CP_WAIT0();
        __syncthreads();
    }

    for (int kc = 0; kc < 32; kc++) {
        const int buf = kc & 1;
        float4 hv[2];
        if (kc < 31) {
            const int k0 = (kc + 1) * 32;
            // issue async W2 stage for next chunk
            const uint32_t dstb = smem_u32(sB + (buf ^ 1) * 256 * SA_PITCH);
#pragma unroll
            for (int t = 0; t < 4; t++) {
                const int idx = t * 512 + tid;
                const int n = idx >> 3, kq = (idx & 7) * 4;
                cp16(dstb + (n * SA_PITCH + kq) * 4,
                     &g_W2T[(size_t)(nbase + n) * 1024 + k0 + kq]);
            }
            CP_COMMIT();
            // h1 prefetch into regs
#pragma unroll
            for (int t = 0; t < 2; t++) {
                const int idx = t * 512 + tid;
                const int m = idx >> 3, kq = (idx & 7) * 4;
                float4 bv = *(const float4*)&g_B[(size_t)(j0 + m) * 1024 + k0 + kq];
                float4 av = *(const float4*)&Arow[k0 + kq];
                hv[t] = make_float4(tf32f(fmaxf(av.x + bv.x, 0.f)),
                                    tf32f(fmaxf(av.y + bv.y, 0.f)),
                                    tf32f(fmaxf(av.z + bv.z, 0.f)),
                                    tf32f(fmaxf(av.w + bv.w, 0.f)));
            }
        }

        // compute current chunk
        const uint32_t* cA = (const uint32_t*)(sA + buf * 128 * SA_PITCH);
        const uint32_t* cB = (const uint32_t*)(sB + buf * 256 * SA_PITCH);
#pragma unroll
        for (int ks = 0; ks < 4; ks++) {
            const int kb = ks * 8;
            uint32_t a[2][4];
#pragma unroll
            for (int mt = 0; mt < 2; mt++) {
                const int r = wm * 32 + mt * 16;
                a[mt][0] = cA[(r + g) * SA_PITCH + kb + tg];
                a[mt][1] = cA[(r + g + 8) * SA_PITCH + kb + tg];
                a[mt][2] = cA[(r + g) * SA_PITCH + kb + tg + 4];
                a[mt][3] = cA[(r + g + 8) * SA_PITCH + kb + tg + 4];
            }
#pragma unroll
            for (int nt = 0; nt < 8; nt++) {
                const int nc = wn * 64 + nt * 8 + g;
                const uint32_t b0 = cB[nc * SA_PITCH + kb + tg];
                const uint32_t b1 = cB[nc * SA_PITCH + kb + tg + 4];
                mma1688(acc[0][nt], a[0], b0, b1);
                mma1688(acc[1][nt], a[1], b0, b1);
            }
        }

        if (kc < 31) {
#pragma unroll
            for (int t = 0; t < 2; t++) {
                const int idx = t * 512 + tid;
                const int m = idx >> 3, kq = (idx & 7) * 4;
                *(float4*)&sA[(buf ^ 1) * 128 * SA_PITCH + m * SA_PITCH + kq] = hv[t];
            }
        }
        CP_WAIT0();
        __syncthreads();
    }

    // epilogue: h2 = tf32(relu(acc + b2))
#pragma unroll
    for (int mt = 0; mt < 2; mt++) {
        const int r = wm * 32 + mt * 16 + g;
#pragma unroll
        for (int nt = 0; nt < 8; nt++) {
            const int col = nbase + wn * 64 + nt * 8 + tg * 2;
            const float ba = __ldg(&b2[col]);
            const float bb = __ldg(&b2[col + 1]);
            float2 v0 = make_float2(tf32f(fmaxf(acc[mt][nt][0] + ba, 0.f)),
                                    tf32f(fmaxf(acc[mt][nt][1] + bb, 0.f)));
            float2 v1 = make_float2(tf32f(fmaxf(acc[mt][nt][2] + ba, 0.f)),
                                    tf32f(fmaxf(acc[mt][nt][3] + bb, 0.f)));
            *(float2*)&g_h2[(r0 + r) * 512 + col]     = v0;
            *(float2*)&g_h2[(r0 + r + 8) * 512 + col] = v1;
        }
    }
}

// ================================================================
// Kernel 4: GEMM3 — out = h2 @ Wo + bo
// CTA: 256 thr, tile M=128 x N=128, K=512 (16 chunks of 32, dbuf).
// Warp grid 4m x 2n, warp tile 32x64.
// ================================================================
#define G3_SMEM ((2 * 128 * SA_PITCH * 2) * 4)

__global__ __launch_bounds__(256, 2) void gemm3(const float* __restrict__ bo,
                                                float* __restrict__ out)
{
    extern __shared__ float sm3[];
    float* sH = sm3;                         // [2][128][36]
    float* sW = sm3 + 2 * 128 * SA_PITCH;    // [2][128][36]

    const int tid = threadIdx.x, w = tid >> 5, l = tid & 31;
    const int g = l >> 2, tg = l & 3;
    const int wm = w >> 1, wn = w & 1;
    const size_t r0 = (size_t)blockIdx.x * 128;

    float acc[2][8][4];
#pragma unroll
    for (int mt = 0; mt < 2; mt++)
#pragma unroll
        for (int nt = 0; nt < 8; nt++)
#pragma unroll
            for (int q = 0; q < 4; q++) acc[mt][nt][q] = 0.f;

    auto stage = [&](int kc, int buf) {
        const int k0 = kc * 32;
        const uint32_t dH = smem_u32(sH + buf * 128 * SA_PITCH);
        const uint32_t dW = smem_u32(sW + buf * 128 * SA_PITCH);
#pragma unroll
        for (int t = 0; t < 4; t++) {
            const int idx = t * 256 + tid;
            const int m = idx >> 3, kq = (idx & 7) * 4;
            cp16(dH + (m * SA_PITCH + kq) * 4, &g_h2[(r0 + m) * 512 + k0 + kq]);
            cp16(dW + (m * SA_PITCH + kq) * 4, &g_WoT[(size_t)m * 512 + k0 + kq]);
        }
        CP_COMMIT();
    };

    stage(0, 0);
    CP_WAIT0();
    __syncthreads();

    for (int kc = 0; kc < 16; kc++) {
        const int buf = kc & 1;
        if (kc < 15) stage(kc + 1, buf ^ 1);

        const uint32_t* cH = (const uint32_t*)(sH + buf * 128 * SA_PITCH);
        const uint32_t* cW = (const uint32_t*)(sW + buf * 128 * SA_PITCH);
#pragma unroll
        for (int ks = 0; ks < 4; ks++) {
            const int kb = ks * 8;
            uint32_t a[2][4];
#pragma unroll
            for (int mt = 0; mt < 2; mt++) {
                const int r = wm * 32 + mt * 16;
                a[mt][0] = cH[(r + g) * SA_PITCH + kb + tg];
                a[mt][1] = cH[(r + g + 8) * SA_PITCH + kb + tg];
                a[mt][2] = cH[(r + g) * SA_PITCH + kb + tg + 4];
                a[mt][3] = cH[(r + g + 8) * SA_PITCH + kb + tg + 4];
            }
#pragma unroll
            for (int nt = 0; nt < 8; nt++) {
                const int nc = wn * 64 + nt * 8 + g;
                const uint32_t b0 = cW[nc * SA_PITCH + kb + tg];
                const uint32_t b1 = cW[nc * SA_PITCH + kb + tg + 4];
                mma1688(acc[0][nt], a[0], b0, b1);
                mma1688(acc[1][nt], a[1], b0, b1);
            }
        }
        CP_WAIT0();
        __syncthreads();
    }

    // epilogue: out = acc + bo
#pragma unroll
    for (int mt = 0; mt < 2; mt++) {
        const int r = wm * 32 + mt * 16 + g;
#pragma unroll
        for (int nt = 0; nt < 8; nt++) {
            const int col = wn * 64 + nt * 8 + tg * 2;
            const float ba = __ldg(&bo[col]);
            const float bb = __ldg(&bo[col + 1]);
            float2 v0 = make_float2(acc[mt][nt][0] + ba, acc[mt][nt][1] + bb);
            float2 v1 = make_float2(acc[mt][nt][2] + ba, acc[mt][nt][3] + bb);
            *(float2*)&out[(r0 + r) * OUTW + col]     = v0;
            *(float2*)&out[(r0 + r + 8) * OUTW + col] = v1;
        }
    }
}

// ================================================================
extern "C" void kernel_launch(void* const* d_in, const int* in_sizes, int n_in,
                              void* d_out, int out_size) {
    const float* emb  = (const float*)d_in[0];
    const int*   bidx = (const int*)  d_in[1];
    const int*   eidx = (const int*)  d_in[2];
    const float* W1   = (const float*)d_in[3];
    const float* b1   = (const float*)d_in[4];
    const float* W2   = (const float*)d_in[5];
    const float* b2   = (const float*)d_in[6];
    const float* Wo   = (const float*)d_in[7];
    const float* bo   = (const float*)d_in[8];
    float* out = (float*)d_out;

    float *w2t_p = nullptr, *wot_p = nullptr;
    cudaGetSymbolAddress((void**)&w2t_p, g_W2T);
    cudaGetSymbolAddress((void**)&wot_p, g_WoT);

    dim3 gA(32, 4);
    precompute_ab<<<gA, 256>>>(emb, bidx, eidx, W1, b1);
    transpose_cvt<<<dim3(16, 32), 256>>>(W2, w2t_p, 1024, 512);
    transpose_cvt<<<dim3(4, 16), 256>>>(Wo, wot_p, 512, 128);

    cudaFuncSetAttribute(gemm2, cudaFuncAttributeMaxDynamicSharedMemorySize, G2_SMEM);
    gemm2<<<1024, 512, G2_SMEM>>>(b2);

    cudaFuncSetAttribute(gemm3, cudaFuncAttributeMaxDynamicSharedMemorySize, G3_SMEM);
    gemm3<<<512, 256, G3_SMEM>>>(bo, out);
}

// round 4
// speedup vs baseline: 5.3767x; 1.8311x over previous
#include <cuda_runtime.h>
#include <cuda_fp16.h>
#include <cstdint>

#define OUTW 128

// ---------------- device scratch ----------------
__device__ float  g_Pp[4][256 * 2048];      // K-split partials (A part n<1024, B part n>=1024)
__device__ float  g_A[256 * 1024];          // left_i @ W1_top   (fp32)
__device__ __half g_Bh[256 * 1024];         // left_j @ W1_bot + b1 (fp16)
__device__ __half g_W2T[512 * 1024];        // W2^T  [N][K] fp16
__device__ __half g_WoT[128 * 512];         // Wo^T  [N][K] fp16
__device__ __half g_h2[65536ull * 512];     // relu(h1@W2+b2) fp16

// ---------------- helpers ----------------
__device__ __forceinline__ uint32_t smem_u32(const void* p) {
    uint32_t a;
    asm("{ .reg .u64 t; cvta.to.shared.u64 t, %1; cvt.u32.u64 %0, t; }"
        : "=r"(a) : "l"(p));
    return a;
}
__device__ __forceinline__ void cp16(uint32_t s, const void* g) {
    asm volatile("cp.async.cg.shared.global [%0], [%1], 16;" :: "r"(s), "l"(g));
}
#define CP_COMMIT() asm volatile("cp.async.commit_group;" ::: "memory")
#define CP_WAIT0()  asm volatile("cp.async.wait_group 0;" ::: "memory")

__device__ __forceinline__ void ldmx4(uint32_t r[4], uint32_t addr) {
    asm volatile("ldmatrix.sync.aligned.m8n8.x4.shared.b16 {%0,%1,%2,%3}, [%4];"
                 : "=r"(r[0]), "=r"(r[1]), "=r"(r[2]), "=r"(r[3]) : "r"(addr));
}
// D += A(16x16 row) * B(16x8 col)  fp16 in, fp32 acc
__device__ __forceinline__ void mma16816(float d[4], const uint32_t a[4],
                                         uint32_t b0, uint32_t b1) {
    asm volatile(
        "mma.sync.aligned.m16n8k16.row.col.f32.f16.f16.f32 "
        "{%0,%1,%2,%3}, {%4,%5,%6,%7}, {%8,%9}, {%0,%1,%2,%3};"
        : "+f"(d[0]), "+f"(d[1]), "+f"(d[2]), "+f"(d[3])
        : "r"(a[0]), "r"(a[1]), "r"(a[2]), "r"(a[3]), "r"(b0), "r"(b1));
}
// swizzled byte offset within a [rows][64 halves] tile (128B rows, 16B chunks)
__device__ __forceinline__ uint32_t tswz(int r, int c) {
    return (uint32_t)(r * 128 + ((c ^ (r & 7)) << 4));
}

// ================================================================
// Kernel 1: K-split precompute (z = 0..3 over 512-wide K slices)
// ================================================================
__global__ __launch_bounds__(256) void precompute_part(
    const float* __restrict__ emb, const int* __restrict__ bidx,
    const int* __restrict__ eidx, const float* __restrict__ W1)
{
    __shared__ float ls[16][68];
    __shared__ float ws[16][64];
    const int n0 = blockIdx.x * 64, m0 = blockIdx.y * 64, z = blockIdx.z;
    const int tid = threadIdx.x, ty = tid >> 4, tx = tid & 15;
    float acc[4][4];
#pragma unroll
    for (int a = 0; a < 4; a++)
#pragma unroll
        for (int b = 0; b < 4; b++) acc[a][b] = 0.f;

    const int lm = tid & 63, lkq = (tid >> 6) * 4;
    const int wk = tid >> 4, wn = (tid & 15) * 4;
    const int erow = (z >= 2 ? eidx : bidx)[m0 + lm];
    const int ecol0 = (z & 1) * 512;
    const int gn = n0 + wn;
    const int wbase = (gn < 1024) ? z * 512 : 2048 + z * 512;
    const int wcol = gn & 1023;

    for (int k0 = 0; k0 < 512; k0 += 16) {
        float4 lv = *(const float4*)&emb[(size_t)erow * 1024 + ecol0 + k0 + lkq];
        ls[lkq + 0][lm] = lv.x; ls[lkq + 1][lm] = lv.y;
        ls[lkq + 2][lm] = lv.z; ls[lkq + 3][lm] = lv.w;
        *(float4*)&ws[wk][wn] = *(const float4*)&W1[(size_t)(wbase + k0 + wk) * 1024 + wcol];
        __syncthreads();
#pragma unroll
        for (int k = 0; k < 16; k++) {
            float a[4], b[4];
            *(float4*)a = *(const float4*)&ls[k][ty * 4];
            *(float4*)b = *(const float4*)&ws[k][tx * 4];
#pragma unroll
            for (int m2 = 0; m2 < 4; m2++)
#pragma unroll
                for (int n2 = 0; n2 < 4; n2++)
                    acc[m2][n2] = fmaf(a[m2], b[n2], acc[m2][n2]);
        }
        __syncthreads();
    }
#pragma unroll
    for (int m2 = 0; m2 < 4; m2++)
#pragma unroll
        for (int n2 = 0; n2 < 4; n2++)
            g_Pp[z][(m0 + ty * 4 + m2) * 2048 + n0 + tx * 4 + n2] = acc[m2][n2];
}

// ================================================================
// Kernel 2: merge partials.  n<1024 -> g_A fp32;  n>=1024 -> g_Bh fp16 (+b1)
// ================================================================
__global__ __launch_bounds__(256) void merge_ab(const float* __restrict__ b1)
{
    const int i4 = blockIdx.x * 256 + threadIdx.x;   // 131072 float4 tasks
    const int m = i4 >> 9, n = (i4 & 511) * 4;
    const size_t off = (size_t)m * 2048 + n;
    float4 p0 = *(const float4*)&g_Pp[0][off];
    float4 p1 = *(const float4*)&g_Pp[1][off];
    float4 p2 = *(const float4*)&g_Pp[2][off];
    float4 p3 = *(const float4*)&g_Pp[3][off];
    float4 s = make_float4(p0.x + p1.x + p2.x + p3.x, p0.y + p1.y + p2.y + p3.y,
                           p0.z + p1.z + p2.z + p3.z, p0.w + p1.w + p2.w + p3.w);
    if (n < 1024) {
        *(float4*)&g_A[m * 1024 + n] = s;
    } else {
        const int nb = n - 1024;
        float4 bv = *(const float4*)&b1[nb];
        __half2 h0 = __floats2half2_rn(s.x + bv.x, s.y + bv.y);
        __half2 h1 = __floats2half2_rn(s.z + bv.z, s.w + bv.w);
        uint2 pk = make_uint2(*(uint32_t*)&h0, *(uint32_t*)&h1);
        *(uint2*)&g_Bh[m * 1024 + nb] = pk;
    }
}

// ================================================================
// Kernel 3: transpose + fp16:  src[R][C] fp32 -> dst[C][R] fp16
// ================================================================
__global__ __launch_bounds__(256) void transpose_cvth(const float* __restrict__ src,
                                                      __half* __restrict__ dst,
                                                      int R, int C)
{
    __shared__ float t[32][33];
    const int c0 = blockIdx.x * 32, r0 = blockIdx.y * 32;
    const int x = threadIdx.x & 31, y = threadIdx.x >> 5;
#pragma unroll
    for (int dy = 0; dy < 32; dy += 8)
        t[y + dy][x] = src[(size_t)(r0 + y + dy) * C + c0 + x];
    __syncthreads();
#pragma unroll
    for (int dy = 0; dy < 32; dy += 8)
        dst[(size_t)(c0 + y + dy) * R + r0 + x] = __float2half_rn(t[x][y + dy]);
}

// ================================================================
// Kernel 4: GEMM2 fp16 — h2 = fp16(relu(h1 @ W2 + b2))
// 512 thr, tile M=128 N=256, K=1024 in 16 chunks of 64, dbuf.
// smem: sA[2][128 rows][128B] = 32KB, sB[2][256][128B] = 64KB.
// Warp grid 4m x 4n, warp tile 32x64: per k16-step 2 A-ldmx4 + 4 B-ldmx4 + 16 mma.
// ================================================================
#define G2_SMEM (32768 + 65536)

__global__ __launch_bounds__(512, 1) void gemm2(const float* __restrict__ b2)
{
    extern __shared__ __align__(16) char sm[];
    char* sA = sm;            // 2 x 16KB
    char* sB = sm + 32768;    // 2 x 32KB
    const uint32_t sAu = smem_u32(sA), sBu = smem_u32(sB);

    const int tid = threadIdx.x, w = tid >> 5, l = tid & 31;
    const int wm = w >> 2, wn = w & 3;

    const int rb = blockIdx.x >> 1, nh = blockIdx.x & 1;
    const size_t r0 = (size_t)rb * 128;
    const int i = rb >> 1, j0 = (rb & 1) * 128, nbase = nh * 256;
    const float* __restrict__ Arow = g_A + (size_t)i * 1024;

    float acc[2][8][4];
#pragma unroll
    for (int mt = 0; mt < 2; mt++)
#pragma unroll
        for (int nt = 0; nt < 8; nt++)
#pragma unroll
            for (int q = 0; q < 4; q++) acc[mt][nt][q] = 0.f;

    // h1 16B-task builder: idx in [0,1024): m = idx>>3, chunk c = idx&7
    auto build16 = [&](int k0, int idx) -> uint4 {
        const int m = idx >> 3, c = idx & 7;
        const int kk = k0 + c * 8;
        uint4 braw = *(const uint4*)&g_Bh[(size_t)(j0 + m) * 1024 + kk];
        const __half2* bh = (const __half2*)&braw;
        float4 a0 = *(const float4*)&Arow[kk];
        float4 a1 = *(const float4*)&Arow[kk + 4];
        float2 f0 = __half22float2(bh[0]), f1 = __half22float2(bh[1]);
        float2 f2 = __half22float2(bh[2]), f3 = __half22float2(bh[3]);
        __half2 h0 = __floats2half2_rn(fmaxf(a0.x + f0.x, 0.f), fmaxf(a0.y + f0.y, 0.f));
        __half2 h1 = __floats2half2_rn(fmaxf(a0.z + f1.x, 0.f), fmaxf(a0.w + f1.y, 0.f));
        __half2 h2v = __floats2half2_rn(fmaxf(a1.x + f2.x, 0.f), fmaxf(a1.y + f2.y, 0.f));
        __half2 h3 = __floats2half2_rn(fmaxf(a1.z + f3.x, 0.f), fmaxf(a1.w + f3.y, 0.f));
        uint4 o;
        o.x = *(uint32_t*)&h0; o.y = *(uint32_t*)&h1;
        o.z = *(uint32_t*)&h2v; o.w = *(uint32_t*)&h3;
        return o;
    };
    auto stageB = [&](int k0, int buf) {
        const uint32_t dst = sBu + buf * 32768;
#pragma unroll
        for (int t = 0; t < 4; t++) {
            const int idx = t * 512 + tid;          // 2048 tasks: n = idx>>3, c = idx&7
            const int n = idx >> 3, c = idx & 7;
            cp16(dst + tswz(n, c),
                 &g_W2T[(size_t)(nbase + n) * 1024 + k0 + c * 8]);
        }
        CP_COMMIT();
    };

    // prologue: chunk 0
    stageB(0, 0);
#pragma unroll
    for (int t = 0; t < 2; t++) {
        const int idx = t * 512 + tid;
        uint4 h = build16(0, idx);
        *(uint4*)(sA + tswz(idx >> 3, idx & 7)) = h;
    }
    CP_WAIT0();
    __syncthreads();

    for (int kc = 0; kc < 16; kc++) {
        const int buf = kc & 1;
        uint4 hv[2];
        if (kc < 15) {
            stageB((kc + 1) * 64, buf ^ 1);
            hv[0] = build16((kc + 1) * 64, tid);
            hv[1] = build16((kc + 1) * 64, 512 + tid);
        }

        const uint32_t cAu = sAu + buf * 16384;
        const uint32_t cBu = sBu + buf * 32768;
        const int lr = l & 15, lc = l >> 4;
#pragma unroll
        for (int ks = 0; ks < 4; ks++) {
            uint32_t a[2][4], b[4][4];
#pragma unroll
            for (int mt = 0; mt < 2; mt++) {
                const int r = wm * 32 + mt * 16 + lr;
                ldmx4(a[mt], cAu + tswz(r, ks * 2 + lc));
            }
#pragma unroll
            for (int nb = 0; nb < 4; nb++) {
                const int r = wn * 64 + nb * 16 + lr;
                ldmx4(b[nb], cBu + tswz(r, ks * 2 + lc));
            }
#pragma unroll
            for (int mt = 0; mt < 2; mt++)
#pragma unroll
                for (int nt = 0; nt < 8; nt++) {
                    const int nb = nt >> 1, hi = nt & 1;
                    mma16816(acc[mt][nt], a[mt], b[nb][hi], b[nb][2 + hi]);
                }
        }

        if (kc < 15) {
            *(uint4*)(sA + (buf ^ 1) * 16384 + tswz(tid >> 3, tid & 7)) = hv[0];
            const int idx = 512 + tid;
            *(uint4*)(sA + (buf ^ 1) * 16384 + tswz(idx >> 3, idx & 7)) = hv[1];
        }
        CP_WAIT0();
        __syncthreads();
    }

    // epilogue: h2 = fp16(relu(acc + b2))
    const int g = l >> 2, tg = l & 3;
#pragma unroll
    for (int mt = 0; mt < 2; mt++) {
        const int r = wm * 32 + mt * 16 + g;
#pragma unroll
        for (int nt = 0; nt < 8; nt++) {
            const int col = nbase + wn * 64 + nt * 8 + tg * 2;
            const float ba = __ldg(&b2[col]);
            const float bb = __ldg(&b2[col + 1]);
            __half2 v0 = __floats2half2_rn(fmaxf(acc[mt][nt][0] + ba, 0.f),
                                           fmaxf(acc[mt][nt][1] + bb, 0.f));
            __half2 v1 = __floats2half2_rn(fmaxf(acc[mt][nt][2] + ba, 0.f),
                                           fmaxf(acc[mt][nt][3] + bb, 0.f));
            *(uint32_t*)&g_h2[(r0 + r) * 512 + col]     = *(uint32_t*)&v0;
            *(uint32_t*)&g_h2[(r0 + r + 8) * 512 + col] = *(uint32_t*)&v1;
        }
    }
}

// ================================================================
// Kernel 5: GEMM3 fp16 — out = h2 @ Wo + bo
// 256 thr, tile M=128 N=128, K=512 in 8 chunks of 64, dbuf, 2 CTA/SM.
// Warp grid 4m x 2n, warp tile 32x64.
// ================================================================
#define G3_SMEM (32768 + 32768)

__global__ __launch_bounds__(256, 2) void gemm3(const float* __restrict__ bo,
                                                float* __restrict__ out)
{
    extern __shared__ __align__(16) char sm3[];
    char* sH = sm3;            // 2 x 16KB
    char* sW = sm3 + 32768;    // 2 x 16KB
    const uint32_t sHu = smem_u32(sH), sWu = smem_u32(sW);

    const int tid = threadIdx.x, w = tid >> 5, l = tid & 31;
    const int wm = w >> 1, wn = w & 1;
    const size_t r0 = (size_t)blockIdx.x * 128;

    float acc[2][8][4];
#pragma unroll
    for (int mt = 0; mt < 2; mt++)
#pragma unroll
        for (int nt = 0; nt < 8; nt++)
#pragma unroll
            for (int q = 0; q < 4; q++) acc[mt][nt][q] = 0.f;

    auto stage = [&](int k0, int buf) {
        const uint32_t dH = sHu + buf * 16384;
        const uint32_t dW = sWu + buf * 16384;
#pragma unroll
        for (int t = 0; t < 4; t++) {
            const int idx = t * 256 + tid;          // 1024 tasks each
            const int m = idx >> 3, c = idx & 7;
            cp16(dH + tswz(m, c), &g_h2[(r0 + m) * 512 + k0 + c * 8]);
            cp16(dW + tswz(m, c), &g_WoT[(size_t)m * 512 + k0 + c * 8]);
        }
        CP_COMMIT();
    };

    stage(0, 0);
    CP_WAIT0();
    __syncthreads();

    for (int kc = 0; kc < 8; kc++) {
        const int buf = kc & 1;
        if (kc < 7) stage((kc + 1) * 64, buf ^ 1);

        const uint32_t cHu = sHu + buf * 16384;
        const uint32_t cWu = sWu + buf * 16384;
        const int lr = l & 15, lc = l >> 4;
#pragma unroll
        for (int ks = 0; ks < 4; ks++) {
            uint32_t a[2][4], b[4][4];
#pragma unroll
            for (int mt = 0; mt < 2; mt++) {
                const int r = wm * 32 + mt * 16 + lr;
                ldmx4(a[mt], cHu + tswz(r, ks * 2 + lc));
            }
#pragma unroll
            for (int nb = 0; nb < 4; nb++) {
                const int r = wn * 64 + nb * 16 + lr;
                ldmx4(b[nb], cWu + tswz(r, ks * 2 + lc));
            }
#pragma unroll
            for (int mt = 0; mt < 2; mt++)
#pragma unroll
                for (int nt = 0; nt < 8; nt++) {
                    const int nb = nt >> 1, hi = nt & 1;
                    mma16816(acc[mt][nt], a[mt], b[nb][hi], b[nb][2 + hi]);
                }
        }
        CP_WAIT0();
        __syncthreads();
    }

    const int g = l >> 2, tg = l & 3;
#pragma unroll
    for (int mt = 0; mt < 2; mt++) {
        const int r = wm * 32 + mt * 16 + g;
#pragma unroll
        for (int nt = 0; nt < 8; nt++) {
            const int col = wn * 64 + nt * 8 + tg * 2;
            const float ba = __ldg(&bo[col]);
            const float bb = __ldg(&bo[col + 1]);
            float2 v0 = make_float2(acc[mt][nt][0] + ba, acc[mt][nt][1] + bb);
            float2 v1 = make_float2(acc[mt][nt][2] + ba, acc[mt][nt][3] + bb);
            *(float2*)&out[(r0 + r) * OUTW + col]     = v0;
            *(float2*)&out[(r0 + r + 8) * OUTW + col] = v1;
        }
    }
}

// ================================================================
extern "C" void kernel_launch(void* const* d_in, const int* in_sizes, int n_in,
                              void* d_out, int out_size) {
    const float* emb  = (const float*)d_in[0];
    const int*   bidx = (const int*)  d_in[1];
    const int*   eidx = (const int*)  d_in[2];
    const float* W1   = (const float*)d_in[3];
    const float* b1   = (const float*)d_in[4];
    const float* W2   = (const float*)d_in[5];
    const float* b2   = (const float*)d_in[6];
    const float* Wo   = (const float*)d_in[7];
    const float* bo   = (const float*)d_in[8];
    float* out = (float*)d_out;

    __half *w2t_p = nullptr, *wot_p = nullptr;
    cudaGetSymbolAddress((void**)&w2t_p, g_W2T);
    cudaGetSymbolAddress((void**)&wot_p, g_WoT);

    precompute_part<<<dim3(32, 4, 4), 256>>>(emb, bidx, eidx, W1);
    merge_ab<<<512, 256>>>(b1);
    transpose_cvth<<<dim3(16, 32), 256>>>(W2, w2t_p, 1024, 512);
    transpose_cvth<<<dim3(4, 16), 256>>>(Wo, wot_p, 512, 128);

    cudaFuncSetAttribute(gemm2, cudaFuncAttributeMaxDynamicSharedMemorySize, G2_SMEM);
    gemm2<<<1024, 512, G2_SMEM>>>(b2);

    cudaFuncSetAttribute(gemm3, cudaFuncAttributeMaxDynamicSharedMemorySize, G3_SMEM);
    gemm3<<<512, 256, G3_SMEM>>>(bo, out);
}

// round 5
// speedup vs baseline: 5.4739x; 1.0181x over previous
#include <cuda_runtime.h>
#include <cuda_fp16.h>
#include <cstdint>

#define OUTW 128

// ---------------- device scratch ----------------
__device__ float  g_Pp[8][256 * 2048];      // K-split partials
__device__ float  g_A[256 * 1024];          // left_i @ W1_top   (fp32)
__device__ __half g_Bh[256 * 1024];         // left_j @ W1_bot + b1 (fp16)
__device__ __half g_W2T[512 * 1024];        // W2^T  [N][K] fp16
__device__ __half g_WoT[128 * 512];         // Wo^T  [N][K] fp16
__device__ __half g_h2[65536ull * 512];     // relu(h1@W2+b2) fp16

// ---------------- helpers ----------------
__device__ __forceinline__ uint32_t smem_u32(const void* p) {
    uint32_t a;
    asm("{ .reg .u64 t; cvta.to.shared.u64 t, %1; cvt.u32.u64 %0, t; }"
        : "=r"(a) : "l"(p));
    return a;
}
__device__ __forceinline__ void cp16(uint32_t s, const void* g) {
    asm volatile("cp.async.cg.shared.global [%0], [%1], 16;" :: "r"(s), "l"(g));
}
#define CP_COMMIT() asm volatile("cp.async.commit_group;" ::: "memory")
#define CP_WAIT0()  asm volatile("cp.async.wait_group 0;" ::: "memory")
#define CP_WAIT1()  asm volatile("cp.async.wait_group 1;" ::: "memory")

__device__ __forceinline__ void ldmx4(uint32_t r[4], uint32_t addr) {
    asm volatile("ldmatrix.sync.aligned.m8n8.x4.shared.b16 {%0,%1,%2,%3}, [%4];"
                 : "=r"(r[0]), "=r"(r[1]), "=r"(r[2]), "=r"(r[3]) : "r"(addr));
}
__device__ __forceinline__ void mma16816(float d[4], const uint32_t a[4],
                                         uint32_t b0, uint32_t b1) {
    asm volatile(
        "mma.sync.aligned.m16n8k16.row.col.f32.f16.f16.f32 "
        "{%0,%1,%2,%3}, {%4,%5,%6,%7}, {%8,%9}, {%0,%1,%2,%3};"
        : "+f"(d[0]), "+f"(d[1]), "+f"(d[2]), "+f"(d[3])
        : "r"(a[0]), "r"(a[1]), "r"(a[2]), "r"(a[3]), "r"(b0), "r"(b1));
}
// swizzled byte offset within a [rows][64 halves] tile (128B rows, 16B chunks)
__device__ __forceinline__ uint32_t tswz(int r, int c) {
    return (uint32_t)(r * 128 + ((c ^ (r & 7)) << 4));
}

// ================================================================
// Kernel 1: K-split precompute (z = 0..7 over 256-wide K slices)
// ================================================================
__global__ __launch_bounds__(256) void precompute_part(
    const float* __restrict__ emb, const int* __restrict__ bidx,
    const int* __restrict__ eidx, const float* __restrict__ W1)
{
    __shared__ float ls[16][68];
    __shared__ float ws[16][64];
    const int n0 = blockIdx.x * 64, m0 = blockIdx.y * 64, z = blockIdx.z;
    const int tid = threadIdx.x, ty = tid >> 4, tx = tid & 15;
    float acc[4][4];
#pragma unroll
    for (int a = 0; a < 4; a++)
#pragma unroll
        for (int b = 0; b < 4; b++) acc[a][b] = 0.f;

    const int lm = tid & 63, lkq = (tid >> 6) * 4;
    const int wk = tid >> 4, wn = (tid & 15) * 4;
    const int erow = (z >= 4 ? eidx : bidx)[m0 + lm];
    const int ecol0 = (z & 3) * 256;
    const int gn = n0 + wn;
    const int wbase = (gn < 1024) ? z * 256 : 2048 + z * 256;
    const int wcol = gn & 1023;

    for (int k0 = 0; k0 < 256; k0 += 16) {
        float4 lv = *(const float4*)&emb[(size_t)erow * 1024 + ecol0 + k0 + lkq];
        ls[lkq + 0][lm] = lv.x; ls[lkq + 1][lm] = lv.y;
        ls[lkq + 2][lm] = lv.z; ls[lkq + 3][lm] = lv.w;
        *(float4*)&ws[wk][wn] = *(const float4*)&W1[(size_t)(wbase + k0 + wk) * 1024 + wcol];
        __syncthreads();
#pragma unroll
        for (int k = 0; k < 16; k++) {
            float a[4], b[4];
            *(float4*)a = *(const float4*)&ls[k][ty * 4];
            *(float4*)b = *(const float4*)&ws[k][tx * 4];
#pragma unroll
            for (int m2 = 0; m2 < 4; m2++)
#pragma unroll
                for (int n2 = 0; n2 < 4; n2++)
                    acc[m2][n2] = fmaf(a[m2], b[n2], acc[m2][n2]);
        }
        __syncthreads();
    }
#pragma unroll
    for (int m2 = 0; m2 < 4; m2++)
#pragma unroll
        for (int n2 = 0; n2 < 4; n2++)
            g_Pp[z][(m0 + ty * 4 + m2) * 2048 + n0 + tx * 4 + n2] = acc[m2][n2];
}

// ================================================================
// Kernel 2: merge partials.  n<1024 -> g_A fp32;  n>=1024 -> g_Bh fp16 (+b1)
// ================================================================
__global__ __launch_bounds__(256) void merge_ab(const float* __restrict__ b1)
{
    const int i4 = blockIdx.x * 256 + threadIdx.x;   // 131072 float4 tasks
    const int m = i4 >> 9, n = (i4 & 511) * 4;
    const size_t off = (size_t)m * 2048 + n;
    float4 s = make_float4(0.f, 0.f, 0.f, 0.f);
#pragma unroll
    for (int z = 0; z < 8; z++) {
        float4 p = *(const float4*)&g_Pp[z][off];
        s.x += p.x; s.y += p.y; s.z += p.z; s.w += p.w;
    }
    if (n < 1024) {
        *(float4*)&g_A[m * 1024 + n] = s;
    } else {
        const int nb = n - 1024;
        float4 bv = *(const float4*)&b1[nb];
        __half2 h0 = __floats2half2_rn(s.x + bv.x, s.y + bv.y);
        __half2 h1 = __floats2half2_rn(s.z + bv.z, s.w + bv.w);
        uint2 pk = make_uint2(*(uint32_t*)&h0, *(uint32_t*)&h1);
        *(uint2*)&g_Bh[m * 1024 + nb] = pk;
    }
}

// ================================================================
// Kernel 3: transpose + fp16:  src[R][C] fp32 -> dst[C][R] fp16
// ================================================================
__global__ __launch_bounds__(256) void transpose_cvth(const float* __restrict__ src,
                                                      __half* __restrict__ dst,
                                                      int R, int C)
{
    __shared__ float t[32][33];
    const int c0 = blockIdx.x * 32, r0 = blockIdx.y * 32;
    const int x = threadIdx.x & 31, y = threadIdx.x >> 5;
#pragma unroll
    for (int dy = 0; dy < 32; dy += 8)
        t[y + dy][x] = src[(size_t)(r0 + y + dy) * C + c0 + x];
    __syncthreads();
#pragma unroll
    for (int dy = 0; dy < 32; dy += 8)
        dst[(size_t)(c0 + y + dy) * R + r0 + x] = __float2half_rn(t[x][y + dy]);
}

// ================================================================
// Kernel 4: GEMM2 fp16 — h2 = fp16(relu(h1 @ W2 + b2))
// 512 thr, tile M=128 N=256, K=1024 in 16 chunks of 64.
// 3-stage pipeline: sA[3][16KB], sB[3][32KB] = 144KB.
// h1 build split: g_B LDG before compute, cvt+STS after compute.
// ================================================================
#define G2_SMEM (3 * 16384 + 3 * 32768)

__global__ __launch_bounds__(512, 1) void gemm2(const float* __restrict__ b2)
{
    extern __shared__ __align__(16) char sm[];
    char* sA = sm;            // 3 x 16KB
    char* sB = sm + 49152;    // 3 x 32KB
    const uint32_t sAu = smem_u32(sA), sBu = smem_u32(sB);

    const int tid = threadIdx.x, w = tid >> 5, l = tid & 31;
    const int wm = w >> 2, wn = w & 3;

    const int rb = blockIdx.x >> 1, nh = blockIdx.x & 1;
    const size_t r0 = (size_t)rb * 128;
    const int i = rb >> 1, j0 = (rb & 1) * 128, nbase = nh * 256;
    const float* __restrict__ Arow = g_A + (size_t)i * 1024;

    float acc[2][8][4];
#pragma unroll
    for (int mt = 0; mt < 2; mt++)
#pragma unroll
        for (int nt = 0; nt < 8; nt++)
#pragma unroll
            for (int q = 0; q < 4; q++) acc[mt][nt][q] = 0.f;

    uint4 braw[2];                                   // g_B prefetch regs
    auto loadB = [&](int k0) {
#pragma unroll
        for (int t = 0; t < 2; t++) {
            const int idx = t * 512 + tid;
            const int m = idx >> 3, c = idx & 7;
            braw[t] = *(const uint4*)&g_Bh[(size_t)(j0 + m) * 1024 + k0 + c * 8];
        }
    };
    auto cvtStore = [&](int k0, int s) {
#pragma unroll
        for (int t = 0; t < 2; t++) {
            const int idx = t * 512 + tid;
            const int m = idx >> 3, c = idx & 7;
            const int kk = k0 + c * 8;
            const __half2* bh = (const __half2*)&braw[t];
            float4 a0 = *(const float4*)&Arow[kk];
            float4 a1 = *(const float4*)&Arow[kk + 4];
            float2 f0 = __half22float2(bh[0]), f1 = __half22float2(bh[1]);
            float2 f2 = __half22float2(bh[2]), f3 = __half22float2(bh[3]);
            __half2 h0 = __floats2half2_rn(fmaxf(a0.x + f0.x, 0.f), fmaxf(a0.y + f0.y, 0.f));
            __half2 h1 = __floats2half2_rn(fmaxf(a0.z + f1.x, 0.f), fmaxf(a0.w + f1.y, 0.f));
            __half2 h2v = __floats2half2_rn(fmaxf(a1.x + f2.x, 0.f), fmaxf(a1.y + f2.y, 0.f));
            __half2 h3 = __floats2half2_rn(fmaxf(a1.z + f3.x, 0.f), fmaxf(a1.w + f3.y, 0.f));
            uint4 o;
            o.x = *(uint32_t*)&h0; o.y = *(uint32_t*)&h1;
            o.z = *(uint32_t*)&h2v; o.w = *(uint32_t*)&h3;
            *(uint4*)(sA + s * 16384 + tswz(m, c)) = o;
        }
    };
    auto stageB = [&](int k0, int s) {
        const uint32_t dst = sBu + s * 32768;
#pragma unroll
        for (int t = 0; t < 4; t++) {
            const int idx = t * 512 + tid;
            const int n = idx >> 3, c = idx & 7;
            cp16(dst + tswz(n, c), &g_W2T[(size_t)(nbase + n) * 1024 + k0 + c * 8]);
        }
        CP_COMMIT();
    };

    // prologue: stages 0, 1
    stageB(0, 0);  loadB(0);  cvtStore(0, 0);
    stageB(64, 1); loadB(64); cvtStore(64, 1);

    const int lr = l & 15, lc = l >> 4;
    for (int kc = 0; kc < 16; kc++) {
        const int s = kc % 3;
        if (kc < 14) { CP_WAIT1(); } else { CP_WAIT0(); }
        __syncthreads();
        if (kc < 14) { stageB((kc + 2) * 64, (kc + 2) % 3); loadB((kc + 2) * 64); }

        const uint32_t cAu = sAu + s * 16384;
        const uint32_t cBu = sBu + s * 32768;
#pragma unroll
        for (int ks = 0; ks < 4; ks++) {
            uint32_t a[2][4], b[4][4];
#pragma unroll
            for (int mt = 0; mt < 2; mt++) {
                const int r = wm * 32 + mt * 16 + lr;
                ldmx4(a[mt], cAu + tswz(r, ks * 2 + lc));
            }
#pragma unroll
            for (int nb = 0; nb < 4; nb++) {
                const int r = wn * 64 + nb * 16 + lr;
                ldmx4(b[nb], cBu + tswz(r, ks * 2 + lc));
            }
#pragma unroll
            for (int mt = 0; mt < 2; mt++)
#pragma unroll
                for (int nt = 0; nt < 8; nt++) {
                    const int nb = nt >> 1, hi = nt & 1;
                    mma16816(acc[mt][nt], a[mt], b[nb][hi], b[nb][2 + hi]);
                }
        }

        if (kc < 14) cvtStore((kc + 2) * 64, (kc + 2) % 3);
    }

    // epilogue: h2 = fp16(relu(acc + b2))
    const int g = l >> 2, tg = l & 3;
#pragma unroll
    for (int mt = 0; mt < 2; mt++) {
        const int r = wm * 32 + mt * 16 + g;
#pragma unroll
        for (int nt = 0; nt < 8; nt++) {
            const int col = nbase + wn * 64 + nt * 8 + tg * 2;
            const float ba = __ldg(&b2[col]);
            const float bb = __ldg(&b2[col + 1]);
            __half2 v0 = __floats2half2_rn(fmaxf(acc[mt][nt][0] + ba, 0.f),
                                           fmaxf(acc[mt][nt][1] + bb, 0.f));
            __half2 v1 = __floats2half2_rn(fmaxf(acc[mt][nt][2] + ba, 0.f),
                                           fmaxf(acc[mt][nt][3] + bb, 0.f));
            *(uint32_t*)&g_h2[(r0 + r) * 512 + col]     = *(uint32_t*)&v0;
            *(uint32_t*)&g_h2[(r0 + r + 8) * 512 + col] = *(uint32_t*)&v1;
        }
    }
}

// ================================================================
// Kernel 5: GEMM3 fp16 — out = h2 @ Wo + bo
// 256 thr, tile M=128 N=128, K=512 in 8 chunks of 64, 3-stage, 2 CTA/SM.
// ================================================================
#define G3_SMEM (3 * 16384 * 2)

__global__ __launch_bounds__(256, 2) void gemm3(const float* __restrict__ bo,
                                                float* __restrict__ out)
{
    extern __shared__ __align__(16) char sm3[];
    char* sH = sm3;            // 3 x 16KB
    char* sW = sm3 + 49152;    // 3 x 16KB
    const uint32_t sHu = smem_u32(sH), sWu = smem_u32(sW);

    const int tid = threadIdx.x, w = tid >> 5, l = tid & 31;
    const int wm = w >> 1, wn = w & 1;
    const size_t r0 = (size_t)blockIdx.x * 128;

    float acc[2][8][4];
#pragma unroll
    for (int mt = 0; mt < 2; mt++)
#pragma unroll
        for (int nt = 0; nt < 8; nt++)
#pragma unroll
            for (int q = 0; q < 4; q++) acc[mt][nt][q] = 0.f;

    auto stage = [&](int k0, int s) {
        const uint32_t dH = sHu + s * 16384;
        const uint32_t dW = sWu + s * 16384;
#pragma unroll
        for (int t = 0; t < 4; t++) {
            const int idx = t * 256 + tid;
            const int m = idx >> 3, c = idx & 7;
            cp16(dH + tswz(m, c), &g_h2[(r0 + m) * 512 + k0 + c * 8]);
            cp16(dW + tswz(m, c), &g_WoT[(size_t)m * 512 + k0 + c * 8]);
        }
        CP_COMMIT();
    };

    stage(0, 0);
    stage(64, 1);

    const int lr = l & 15, lc = l >> 4;
    for (int kc = 0; kc < 8; kc++) {
        const int s = kc % 3;
        if (kc < 6) { CP_WAIT1(); } else { CP_WAIT0(); }
        __syncthreads();
        if (kc < 6) stage((kc + 2) * 64, (kc + 2) % 3);

        const uint32_t cHu = sHu + s * 16384;
        const uint32_t cWu = sWu + s * 16384;
#pragma unroll
        for (int ks = 0; ks < 4; ks++) {
            uint32_t a[2][4], b[4][4];
#pragma unroll
            for (int mt = 0; mt < 2; mt++) {
                const int r = wm * 32 + mt * 16 + lr;
                ldmx4(a[mt], cHu + tswz(r, ks * 2 + lc));
            }
#pragma unroll
            for (int nb = 0; nb < 4; nb++) {
                const int r = wn * 64 + nb * 16 + lr;
                ldmx4(b[nb], cWu + tswz(r, ks * 2 + lc));
            }
#pragma unroll
            for (int mt = 0; mt < 2; mt++)
#pragma unroll
                for (int nt = 0; nt < 8; nt++) {
                    const int nb = nt >> 1, hi = nt & 1;
                    mma16816(acc[mt][nt], a[mt], b[nb][hi], b[nb][2 + hi]);
                }
        }
    }

    const int g = l >> 2, tg = l & 3;
#pragma unroll
    for (int mt = 0; mt < 2; mt++) {
        const int r = wm * 32 + mt * 16 + g;
#pragma unroll
        for (int nt = 0; nt < 8; nt++) {
            const int col = wn * 64 + nt * 8 + tg * 2;
            const float ba = __ldg(&bo[col]);
            const float bb = __ldg(&bo[col + 1]);
            float2 v0 = make_float2(acc[mt][nt][0] + ba, acc[mt][nt][1] + bb);
            float2 v1 = make_float2(acc[mt][nt][2] + ba, acc[mt][nt][3] + bb);
            *(float2*)&out[(r0 + r) * OUTW + col]     = v0;
            *(float2*)&out[(r0 + r + 8) * OUTW + col] = v1;
        }
    }
}

// ================================================================
extern "C" void kernel_launch(void* const* d_in, const int* in_sizes, int n_in,
                              void* d_out, int out_size) {
    const float* emb  = (const float*)d_in[0];
    const int*   bidx = (const int*)  d_in[1];
    const int*   eidx = (const int*)  d_in[2];
    const float* W1   = (const float*)d_in[3];
    const float* b1   = (const float*)d_in[4];
    const float* W2   = (const float*)d_in[5];
    const float* b2   = (const float*)d_in[6];
    const float* Wo   = (const float*)d_in[7];
    const float* bo   = (const float*)d_in[8];
    float* out = (float*)d_out;

    __half *w2t_p = nullptr, *wot_p = nullptr;
    cudaGetSymbolAddress((void**)&w2t_p, g_W2T);
    cudaGetSymbolAddress((void**)&wot_p, g_WoT);

    precompute_part<<<dim3(32, 4, 8), 256>>>(emb, bidx, eidx, W1);
    merge_ab<<<512, 256>>>(b1);
    transpose_cvth<<<dim3(16, 32), 256>>>(W2, w2t_p, 1024, 512);
    transpose_cvth<<<dim3(4, 16), 256>>>(Wo, wot_p, 512, 128);

    cudaFuncSetAttribute(gemm2, cudaFuncAttributeMaxDynamicSharedMemorySize, G2_SMEM);
    gemm2<<<1024, 512, G2_SMEM>>>(b2);

    cudaFuncSetAttribute(gemm3, cudaFuncAttributeMaxDynamicSharedMemorySize, G3_SMEM);
    gemm3<<<512, 256, G3_SMEM>>>(bo, out);
}